// round 3
// baseline (speedup 1.0000x reference)
#include <cuda_runtime.h>
#include <math.h>
#include <stdint.h>

#define B_    8
#define CIN   256
#define COUT  256
#define HH    64
#define WW    64
#define HW    4096
#define K2    9
#define KTOT  (CIN * K2)   // 2304

typedef unsigned long long ull;

// Scratch: per (b, k, pixel): 4 corner indices + 4 corner weights (mask-premultiplied)
__device__ int   g_cidx[B_ * K2 * HW * 4];
__device__ float g_cwgt[B_ * K2 * HW * 4];
// Pre-transposed main weight: [kt = c*9+k][oc]
__device__ float g_wT[KTOT * COUT];

// ---------------- packed fp32x2 helpers (Blackwell dual-rate fp32) ----------------
__device__ __forceinline__ ull fma2(ull a, ull b, ull c) {
    ull d;
    asm("fma.rn.f32x2 %0, %1, %2, %3;" : "=l"(d) : "l"(a), "l"(b), "l"(c));
    return d;
}
__device__ __forceinline__ ull pack2(float lo, float hi) {
    ull r;
    asm("mov.b64 %0, {%1, %2};" : "=l"(r) : "f"(lo), "f"(hi));
    return r;
}
__device__ __forceinline__ void unpack2(ull v, float& lo, float& hi) {
    asm("mov.b64 {%0, %1}, %2;" : "=f"(lo), "=f"(hi) : "l"(v));
}
__device__ __forceinline__ void cpa16(uint32_t dst, const void* src) {
    asm volatile("cp.async.ca.shared.global [%0], [%1], 16;" :: "r"(dst), "l"(src));
}

// =====================================================================
// Kernel 0: transpose weight [COUT][KTOT] -> g_wT [KTOT][COUT]
// =====================================================================
__global__ void __launch_bounds__(256) transpose_w(const float* __restrict__ wgt)
{
    __shared__ float t[32][33];
    const int kt0 = blockIdx.x * 32;
    const int oc0 = blockIdx.y * 32;
    const int tx = threadIdx.x, ty = threadIdx.y;   // 32 x 8
#pragma unroll
    for (int r = ty; r < 32; r += 8)
        t[r][tx] = wgt[(size_t)(oc0 + r) * KTOT + kt0 + tx];
    __syncthreads();
#pragma unroll
    for (int r = ty; r < 32; r += 8)
        g_wT[(size_t)(kt0 + r) * COUT + oc0 + tx] = t[tx][r];
}

// =====================================================================
// Stage 1: offset(18ch) + mask(9ch) 3x3 conv, fused epilogue that emits
// bilinear corner indices/weights (weights premultiplied by the mask).
// =====================================================================
__global__ void __launch_bounds__(128) prep_kernel(
    const float* __restrict__ x,
    const float* __restrict__ offw, const float* __restrict__ offb,
    const float* __restrict__ modw, const float* __restrict__ modb)
{
    __shared__ float xs[10][18];     // (8+2) x (16+2) halo tile
    __shared__ float ws2[9 * 28];    // [k][oc padded to 28]

    const int b  = blockIdx.z;
    const int h0 = blockIdx.y * 8;
    const int w0 = blockIdx.x * 16;
    const int tid = threadIdx.x;
    const int th = tid >> 4, tw = tid & 15;
    const int h = h0 + th, w = w0 + tw;
    const float* xb = x + (size_t)b * CIN * HW;

    ull acc2[14];
#pragma unroll
    for (int i = 0; i < 14; i++) acc2[i] = 0ull;

    for (int c = 0; c < CIN; c++) {
        for (int i = tid; i < 180; i += 128) {
            int r = i / 18, cc = i - r * 18;
            int gh = h0 - 1 + r, gw = w0 - 1 + cc;
            float v = 0.f;
            if (gh >= 0 && gh < HH && gw >= 0 && gw < WW) v = xb[c * HW + gh * WW + gw];
            (&xs[0][0])[i] = v;
        }
        for (int i = tid; i < 252; i += 128) {
            int k = i / 28, oc = i - k * 28;
            float v;
            if (oc < 18)      v = offw[(oc * CIN + c) * 9 + k];
            else if (oc < 27) v = modw[((oc - 18) * CIN + c) * 9 + k];
            else              v = 0.f;
            ws2[i] = v;
        }
        __syncthreads();

        ull wd[9];
#pragma unroll
        for (int k = 0; k < 9; k++) {
            float v = xs[th + k / 3][tw + k % 3];
            wd[k] = pack2(v, v);
        }
#pragma unroll
        for (int k = 0; k < 9; k++) {
            const float* row = ws2 + k * 28;
#pragma unroll
            for (int u = 0; u < 7; u++) {
                ulonglong2 tt = *(const ulonglong2*)(row + u * 4);
                acc2[2 * u]     = fma2(wd[k], tt.x, acc2[2 * u]);
                acc2[2 * u + 1] = fma2(wd[k], tt.y, acc2[2 * u + 1]);
            }
        }
        __syncthreads();
    }

    float acc[28];
#pragma unroll
    for (int u = 0; u < 14; u++) unpack2(acc2[u], acc[2 * u], acc[2 * u + 1]);

    const int pix = h * WW + w;
#pragma unroll
    for (int k = 0; k < 9; k++) {
        float dy = acc[2 * k]     + offb[2 * k];
        float dx = acc[2 * k + 1] + offb[2 * k + 1];
        float mz = acc[18 + k]    + modb[k];
        float m  = 2.f / (1.f + expf(-mz));

        float py = dy + (float)(h - 1 + k / 3);
        float px = dx + (float)(w - 1 + (k % 3));
        float y0f = floorf(py), x0f = floorf(px);
        float ly = py - y0f, lx = px - x0f;
        int y0 = (int)y0f, x0 = (int)x0f;

        int4 id; float4 wt;
        {
            int yy = y0, xx = x0; float wv = (1.f - ly) * (1.f - lx);
            bool v = (yy >= 0) && (yy < HH) && (xx >= 0) && (xx < WW);
            id.x = min(max(yy, 0), HH - 1) * WW + min(max(xx, 0), WW - 1);
            wt.x = v ? wv * m : 0.f;
        }
        {
            int yy = y0, xx = x0 + 1; float wv = (1.f - ly) * lx;
            bool v = (yy >= 0) && (yy < HH) && (xx >= 0) && (xx < WW);
            id.y = min(max(yy, 0), HH - 1) * WW + min(max(xx, 0), WW - 1);
            wt.y = v ? wv * m : 0.f;
        }
        {
            int yy = y0 + 1, xx = x0; float wv = ly * (1.f - lx);
            bool v = (yy >= 0) && (yy < HH) && (xx >= 0) && (xx < WW);
            id.z = min(max(yy, 0), HH - 1) * WW + min(max(xx, 0), WW - 1);
            wt.z = v ? wv * m : 0.f;
        }
        {
            int yy = y0 + 1, xx = x0 + 1; float wv = ly * lx;
            bool v = (yy >= 0) && (yy < HH) && (xx >= 0) && (xx < WW);
            id.w = min(max(yy, 0), HH - 1) * WW + min(max(xx, 0), WW - 1);
            wt.w = v ? wv * m : 0.f;
        }
        int slot = (b * K2 + k) * HW + pix;
        ((int4*)g_cidx)[slot]   = id;
        ((float4*)g_cwgt)[slot] = wt;
    }
}

// =====================================================================
// Stage 2: fused im2col + GEMM. 512 threads (16 warps):
//   thread = 4 pixels x 8 ocs  (acc = 16 x f32x2 = 32 regs)
//   warp   = 16 pixel-lanes x 2 oc-groups -> S reads broadcast-merge
// Pipelined: cp.async W(next) + register-prefetched gathers(next)
// overlap the FFMA2 GEMM of the current chunk. No spills (<128 regs).
// =====================================================================
#define KC  36
#define NTH 512
// smem layout (floats)
#define SM_SAMPW 0
#define SM_SAMPI 2304
#define SM_S0    4608
#define SM_S1    9216
#define SM_W0    13824
#define SM_W1    23040
#define SMEM_FLOATS 32256          // 129024 bytes

__global__ void __launch_bounds__(NTH) dconv_kernel(
    const float* __restrict__ x,
    const float* __restrict__ bias, float* __restrict__ out)
{
    extern __shared__ float sm[];
    float* sampW = sm + SM_SAMPW;
    int*   sampI = (int*)(sm + SM_SAMPI);
    float* Sb[2] = { sm + SM_S0, sm + SM_S1 };
    float* Wb[2] = { sm + SM_W0, sm + SM_W1 };
    uint32_t Wb_u32[2] = {
        (uint32_t)__cvta_generic_to_shared(sm + SM_W0),
        (uint32_t)__cvta_generic_to_shared(sm + SM_W1)
    };

    const int b = blockIdx.z;
    const int pixbase = blockIdx.x * 64;
    const int tid = threadIdx.x;
    const int L   = tid & 15;           // pixel lane: pixels L*4 .. L*4+3
    const int oc0 = (tid >> 4) * 8;     // 8 output channels / thread
    const float* xb = x + (size_t)b * CIN * HW;

    // cache sampling tables for this block's 64 pixels
    for (int i = tid; i < 576; i += NTH) {
        int k = i >> 6, pix = i & 63;
        int slot = (b * K2 + k) * HW + pixbase + pix;
        ((float4*)sampW)[i] = ((const float4*)g_cwgt)[slot];
        ((int4*)sampI)[i]   = ((const int4*)g_cidx)[slot];
    }

    ull acc2[16];     // [pixel j 0..3][oc-pair o2 0..3]
#pragma unroll
    for (int o2 = 0; o2 < 4; o2++) {
        float2 bb = *(const float2*)(bias + oc0 + 2 * o2);
        ull bv = pack2(bb.x, bb.y);
#pragma unroll
        for (int j = 0; j < 4; j++) acc2[j * 4 + o2] = bv;
    }

    __syncthreads();   // samp tables visible before first prefetch

    float pre[20];     // up to 5 samples x 4 corners

    // ---- stage chunk 0 ----
    {
#pragma unroll
        for (int t = 0; t < 5; t++) {
            int j = tid + t * NTH;
            if (j < 2304) cpa16(Wb_u32[0] + j * 16, g_wT + j * 4);
        }
        asm volatile("cp.async.commit_group;" ::: "memory");
#pragma unroll
        for (int r = 0; r < 5; r++) {
            int i = tid + r * NTH;
            if (i < 2304) {
                int kk = i >> 6, pix = i & 63;
                int cidx = kk / 9, k = kk - cidx * 9;
                int si = (k << 6) + pix;
                int4 i4 = ((const int4*)sampI)[si];
                const float* xp = xb + cidx * HW;
                pre[4 * r + 0] = xp[i4.x];
                pre[4 * r + 1] = xp[i4.y];
                pre[4 * r + 2] = xp[i4.z];
                pre[4 * r + 3] = xp[i4.w];
            }
        }
#pragma unroll
        for (int r = 0; r < 5; r++) {
            int i = tid + r * NTH;
            if (i < 2304) {
                int kk = i >> 6, pix = i & 63;
                int cidx = kk / 9, k = kk - cidx * 9;
                int si = (k << 6) + pix;
                float4 w4 = ((const float4*)sampW)[si];
                float v = w4.x * pre[4 * r + 0] + w4.y * pre[4 * r + 1]
                        + w4.z * pre[4 * r + 2] + w4.w * pre[4 * r + 3];
                *(float2*)(Sb[0] + kk * 128 + pix * 2) = make_float2(v, v);
            }
        }
        asm volatile("cp.async.wait_group 0;" ::: "memory");
    }
    __syncthreads();

    for (int c = 0; c < 64; c++) {
        const int cur = c & 1;
        const int nxt = cur ^ 1;

        if (c < 63) {
            const float* wsrc = g_wT + (size_t)(c + 1) * 9216;
#pragma unroll
            for (int t = 0; t < 5; t++) {
                int j = tid + t * NTH;
                if (j < 2304) cpa16(Wb_u32[nxt] + j * 16, wsrc + j * 4);
            }
            asm volatile("cp.async.commit_group;" ::: "memory");
            const float* xc = xb + (size_t)(c + 1) * 4 * HW;
#pragma unroll
            for (int r = 0; r < 5; r++) {
                int i = tid + r * NTH;
                if (i < 2304) {
                    int kk = i >> 6, pix = i & 63;
                    int cidx = kk / 9, k = kk - cidx * 9;
                    int si = (k << 6) + pix;
                    int4 i4 = ((const int4*)sampI)[si];
                    const float* xp = xc + cidx * HW;
                    pre[4 * r + 0] = xp[i4.x];
                    pre[4 * r + 1] = xp[i4.y];
                    pre[4 * r + 2] = xp[i4.z];
                    pre[4 * r + 3] = xp[i4.w];
                }
            }
        }

        // ---- GEMM on current buffers ----
        const float* Scur = Sb[cur];
        const float* Wcur = Wb[cur];
#pragma unroll 4
        for (int kk = 0; kk < KC; kk++) {
            const float* wrow = Wcur + kk * 256 + oc0;
            ulonglong2 b01 = *(const ulonglong2*)(wrow);
            ulonglong2 b23 = *(const ulonglong2*)(wrow + 4);
            const float* srow = Scur + kk * 128 + L * 8;
            ulonglong2 a01 = *(const ulonglong2*)(srow);
            ulonglong2 a23 = *(const ulonglong2*)(srow + 4);

            acc2[0]  = fma2(a01.x, b01.x, acc2[0]);
            acc2[1]  = fma2(a01.x, b01.y, acc2[1]);
            acc2[2]  = fma2(a01.x, b23.x, acc2[2]);
            acc2[3]  = fma2(a01.x, b23.y, acc2[3]);
            acc2[4]  = fma2(a01.y, b01.x, acc2[4]);
            acc2[5]  = fma2(a01.y, b01.y, acc2[5]);
            acc2[6]  = fma2(a01.y, b23.x, acc2[6]);
            acc2[7]  = fma2(a01.y, b23.y, acc2[7]);
            acc2[8]  = fma2(a23.x, b01.x, acc2[8]);
            acc2[9]  = fma2(a23.x, b01.y, acc2[9]);
            acc2[10] = fma2(a23.x, b23.x, acc2[10]);
            acc2[11] = fma2(a23.x, b23.y, acc2[11]);
            acc2[12] = fma2(a23.y, b01.x, acc2[12]);
            acc2[13] = fma2(a23.y, b01.y, acc2[13]);
            acc2[14] = fma2(a23.y, b23.x, acc2[14]);
            acc2[15] = fma2(a23.y, b23.y, acc2[15]);
        }

        if (c < 63) {
            float* Sn = Sb[nxt];
#pragma unroll
            for (int r = 0; r < 5; r++) {
                int i = tid + r * NTH;
                if (i < 2304) {
                    int kk = i >> 6, pix = i & 63;
                    int cidx = kk / 9, k = kk - cidx * 9;
                    int si = (k << 6) + pix;
                    float4 w4 = ((const float4*)sampW)[si];
                    float v = w4.x * pre[4 * r + 0] + w4.y * pre[4 * r + 1]
                            + w4.z * pre[4 * r + 2] + w4.w * pre[4 * r + 3];
                    *(float2*)(Sn + kk * 128 + pix * 2) = make_float2(v, v);
                }
            }
            asm volatile("cp.async.wait_group 0;" ::: "memory");
        }
        __syncthreads();
    }

    // epilogue: acc2[j][o2] holds (oc0+2*o2, oc0+2*o2+1) for pixel L*4+j
    float* ob = out + (size_t)b * COUT * HW + pixbase;
#pragma unroll
    for (int j = 0; j < 4; j++) {
        int p = L * 4 + j;
#pragma unroll
        for (int o2 = 0; o2 < 4; o2++) {
            float lo, hi;
            unpack2(acc2[j * 4 + o2], lo, hi);
            int oc = oc0 + 2 * o2;
            ob[(size_t)oc * HW + p]       = lo;
            ob[(size_t)(oc + 1) * HW + p] = hi;
        }
    }
}

extern "C" void kernel_launch(void* const* d_in, const int* in_sizes, int n_in,
                              void* d_out, int out_size)
{
    const float* x    = (const float*)d_in[0];
    const float* offw = (const float*)d_in[1];
    const float* offb = (const float*)d_in[2];
    const float* modw = (const float*)d_in[3];
    const float* modb = (const float*)d_in[4];
    const float* wgt  = (const float*)d_in[5];
    const float* bias = (const float*)d_in[6];
    float* out = (float*)d_out;

    cudaFuncSetAttribute(dconv_kernel, cudaFuncAttributeMaxDynamicSharedMemorySize,
                         SMEM_FLOATS * 4);

    dim3 gt(KTOT / 32, COUT / 32);
    transpose_w<<<gt, dim3(32, 8)>>>(wgt);

    dim3 g1(4, 8, 8);       // w-tiles, h-tiles, batch
    prep_kernel<<<g1, 128>>>(x, offw, offb, modw, modb);

    dim3 g2(64, 1, 8);      // one 64-pixel row per block, batch
    dconv_kernel<<<g2, NTH, SMEM_FLOATS * 4>>>(x, bias, out);
}

// round 6
// speedup vs baseline: 2.6248x; 2.6248x over previous
#include <cuda_runtime.h>
#include <cuda_bf16.h>
#include <math.h>
#include <stdint.h>

#define B_    8
#define CIN   256
#define COUT  256
#define HH    64
#define WW    64
#define HW    4096
#define K2    9
#define KTOT  (CIN * K2)   // 2304
#define NCH   72           // K chunks of 32

typedef unsigned long long ull;

// Scratch: per (b, k, pixel): 4 corner indices + 4 corner weights (mask-premultiplied)
__device__ int   g_cidx[B_ * K2 * HW * 4];
__device__ float g_cwgt[B_ * K2 * HW * 4];
// Pre-split weights, chunked: [chunk][hi 16KB | lo 16KB]; row=oc (64B = 32 bf16)
__device__ unsigned char g_wB[NCH * 32768];

// ---------------- helpers ----------------
__device__ __forceinline__ ull fma2(ull a, ull b, ull c) {
    ull d;
    asm("fma.rn.f32x2 %0, %1, %2, %3;" : "=l"(d) : "l"(a), "l"(b), "l"(c));
    return d;
}
__device__ __forceinline__ ull pack2(float lo, float hi) {
    ull r;
    asm("mov.b64 %0, {%1, %2};" : "=l"(r) : "f"(lo), "f"(hi));
    return r;
}
__device__ __forceinline__ void unpack2(ull v, float& lo, float& hi) {
    asm("mov.b64 {%0, %1}, %2;" : "=f"(lo), "=f"(hi) : "l"(v));
}
__device__ __forceinline__ uint32_t smem_u32(const void* p) {
    return (uint32_t)__cvta_generic_to_shared(p);
}
__device__ __forceinline__ void cpa16(uint32_t dst, const void* src) {
    asm volatile("cp.async.ca.shared.global [%0], [%1], 16;" :: "r"(dst), "l"(src));
}
__device__ __forceinline__ void ldm_x4(uint32_t addr, uint32_t* r) {
    asm volatile("ldmatrix.sync.aligned.m8n8.x4.shared.b16 {%0,%1,%2,%3}, [%4];"
                 : "=r"(r[0]), "=r"(r[1]), "=r"(r[2]), "=r"(r[3]) : "r"(addr));
}
__device__ __forceinline__ void mma_bf16(float* d, const uint32_t* a,
                                         uint32_t b0, uint32_t b1) {
    asm volatile("mma.sync.aligned.m16n8k16.row.col.f32.bf16.bf16.f32 "
                 "{%0,%1,%2,%3}, {%4,%5,%6,%7}, {%8,%9}, {%0,%1,%2,%3};"
                 : "+f"(d[0]), "+f"(d[1]), "+f"(d[2]), "+f"(d[3])
                 : "r"(a[0]), "r"(a[1]), "r"(a[2]), "r"(a[3]), "r"(b0), "r"(b1));
}

// =====================================================================
// Kernel 0: split main weight to bf16 hi/lo, chunked layout for cp.async
// =====================================================================
__global__ void __launch_bounds__(256) prep_wB(const float* __restrict__ wgt)
{
    int i = blockIdx.x * 256 + threadIdx.x;    // 72*256*32 = 589824
    int ktl = i & 31;
    int oc  = (i >> 5) & 255;
    int cc  = i >> 13;
    int kt  = cc * 32 + ktl;
    int c   = kt / 9;
    int k   = kt - c * 9;
    float v = wgt[((size_t)oc * CIN + c) * 9 + k];
    __nv_bfloat16 h = __float2bfloat16(v);
    float r = v - __bfloat162float(h);
    __nv_bfloat16 l = __float2bfloat16(r);
    unsigned char* base = g_wB + (size_t)cc * 32768;
    *(unsigned short*)(base + oc * 64 + ktl * 2)         = __bfloat16_as_ushort(h);
    *(unsigned short*)(base + 16384 + oc * 64 + ktl * 2) = __bfloat16_as_ushort(l);
}

// =====================================================================
// Stage 1: offset(18ch) + mask(9ch) 3x3 conv, fused epilogue that emits
// bilinear corner indices/weights (weights premultiplied by the mask).
// =====================================================================
__global__ void __launch_bounds__(128) prep_kernel(
    const float* __restrict__ x,
    const float* __restrict__ offw, const float* __restrict__ offb,
    const float* __restrict__ modw, const float* __restrict__ modb)
{
    __shared__ float xs[10][18];
    __shared__ float ws2[9 * 28];

    const int b  = blockIdx.z;
    const int h0 = blockIdx.y * 8;
    const int w0 = blockIdx.x * 16;
    const int tid = threadIdx.x;
    const int th = tid >> 4, tw = tid & 15;
    const int h = h0 + th, w = w0 + tw;
    const float* xb = x + (size_t)b * CIN * HW;

    ull acc2[14];
#pragma unroll
    for (int i = 0; i < 14; i++) acc2[i] = 0ull;

    for (int c = 0; c < CIN; c++) {
        for (int i = tid; i < 180; i += 128) {
            int r = i / 18, cc = i - r * 18;
            int gh = h0 - 1 + r, gw = w0 - 1 + cc;
            float v = 0.f;
            if (gh >= 0 && gh < HH && gw >= 0 && gw < WW) v = xb[c * HW + gh * WW + gw];
            (&xs[0][0])[i] = v;
        }
        for (int i = tid; i < 252; i += 128) {
            int k = i / 28, oc = i - k * 28;
            float v;
            if (oc < 18)      v = offw[(oc * CIN + c) * 9 + k];
            else if (oc < 27) v = modw[((oc - 18) * CIN + c) * 9 + k];
            else              v = 0.f;
            ws2[i] = v;
        }
        __syncthreads();

        ull wd[9];
#pragma unroll
        for (int k = 0; k < 9; k++) {
            float v = xs[th + k / 3][tw + k % 3];
            wd[k] = pack2(v, v);
        }
#pragma unroll
        for (int k = 0; k < 9; k++) {
            const float* row = ws2 + k * 28;
#pragma unroll
            for (int u = 0; u < 7; u++) {
                ulonglong2 tt = *(const ulonglong2*)(row + u * 4);
                acc2[2 * u]     = fma2(wd[k], tt.x, acc2[2 * u]);
                acc2[2 * u + 1] = fma2(wd[k], tt.y, acc2[2 * u + 1]);
            }
        }
        __syncthreads();
    }

    float acc[28];
#pragma unroll
    for (int u = 0; u < 14; u++) unpack2(acc2[u], acc[2 * u], acc[2 * u + 1]);

    const int pix = h * WW + w;
#pragma unroll
    for (int k = 0; k < 9; k++) {
        float dy = acc[2 * k]     + offb[2 * k];
        float dx = acc[2 * k + 1] + offb[2 * k + 1];
        float mz = acc[18 + k]    + modb[k];
        float m  = 2.f / (1.f + expf(-mz));

        float py = dy + (float)(h - 1 + k / 3);
        float px = dx + (float)(w - 1 + (k % 3));
        float y0f = floorf(py), x0f = floorf(px);
        float ly = py - y0f, lx = px - x0f;
        int y0 = (int)y0f, x0 = (int)x0f;

        int4 id; float4 wt;
        {
            int yy = y0, xx = x0; float wv = (1.f - ly) * (1.f - lx);
            bool v = (yy >= 0) && (yy < HH) && (xx >= 0) && (xx < WW);
            id.x = min(max(yy, 0), HH - 1) * WW + min(max(xx, 0), WW - 1);
            wt.x = v ? wv * m : 0.f;
        }
        {
            int yy = y0, xx = x0 + 1; float wv = (1.f - ly) * lx;
            bool v = (yy >= 0) && (yy < HH) && (xx >= 0) && (xx < WW);
            id.y = min(max(yy, 0), HH - 1) * WW + min(max(xx, 0), WW - 1);
            wt.y = v ? wv * m : 0.f;
        }
        {
            int yy = y0 + 1, xx = x0; float wv = ly * (1.f - lx);
            bool v = (yy >= 0) && (yy < HH) && (xx >= 0) && (xx < WW);
            id.z = min(max(yy, 0), HH - 1) * WW + min(max(xx, 0), WW - 1);
            wt.z = v ? wv * m : 0.f;
        }
        {
            int yy = y0 + 1, xx = x0 + 1; float wv = ly * lx;
            bool v = (yy >= 0) && (yy < HH) && (xx >= 0) && (xx < WW);
            id.w = min(max(yy, 0), HH - 1) * WW + min(max(xx, 0), WW - 1);
            wt.w = v ? wv * m : 0.f;
        }
        int slot = (b * K2 + k) * HW + pix;
        ((int4*)g_cidx)[slot]   = id;
        ((float4*)g_cwgt)[slot] = wt;
    }
}

// =====================================================================
// Stage 2: fused im2col + 3-pass split-bf16 warp-MMA GEMM.
// Block: 128 pixels x 256 ocs, 512 thr / 16 warps (warp tile 32x64).
// K in 72 chunks of 32. A/B tiles 80B-padded rows (conflict-free ldmatrix).
// =====================================================================
#define NTH 512
#define APAD 80
#define BPAD 80
// smem byte offsets
#define SM_SAMPW 0          // 18432
#define SM_SAMPI 18432      // 9216
#define SM_A     27648      // Ahi 10240 | Alo 10240
#define SM_B     48128      // Bhi 20480 | Blo 20480
#define SMEM_BYTES 89088

__global__ void __launch_bounds__(NTH)
dconv_kernel(const float* __restrict__ x,
             const float* __restrict__ bias, float* __restrict__ out)
{
    extern __shared__ unsigned char sm[];
    const uint32_t smb = smem_u32(sm);
    float*  sampW = (float*)(sm + SM_SAMPW);
    short4* sampI = (short4*)(sm + SM_SAMPI);

    const int b = blockIdx.z;
    const int pixbase = blockIdx.x * 128;
    const int tid = threadIdx.x;
    const int lane = tid & 31;
    const int wid = tid >> 5;
    const int warp_m = (wid & 3) * 32;
    const int warp_n = (wid >> 2) * 64;
    const float* xb = x + (size_t)b * CIN * HW;

    // sampling tables for this block's 128 pixels
    for (int i = tid; i < 1152; i += NTH) {
        int k = i >> 7, p = i & 127;
        int slot = (b * K2 + k) * HW + pixbase + p;
        ((float4*)sampW)[i] = ((const float4*)g_cwgt)[slot];
        int4 id = ((const int4*)g_cidx)[slot];
        short4 s;
        s.x = (short)id.x; s.y = (short)id.y; s.z = (short)id.z; s.w = (short)id.w;
        sampI[i] = s;
    }
    __syncthreads();

    float acc[2][8][4];
#pragma unroll
    for (int mt = 0; mt < 2; mt++)
#pragma unroll
        for (int nb = 0; nb < 8; nb++)
#pragma unroll
            for (int r = 0; r < 4; r++) acc[mt][nb][r] = 0.f;

    const uint32_t Au = smb + SM_A;
    const uint32_t Bu = smb + SM_B;

    for (int c = 0; c < NCH; c++) {
        if (c) __syncthreads();    // previous GEMM done before overwriting tiles

        // ---- produce A tile: 2 quads of 4 kt-samples per thread ----
#pragma unroll
        for (int j = 0; j < 2; j++) {
            int q = j * NTH + tid;          // 0..1023
            int p = q & 127;
            int ktq = q >> 7;               // 0..7
            unsigned short hs[4], ls[4];
#pragma unroll
            for (int s = 0; s < 4; s++) {
                int kt = c * 32 + ktq * 4 + s;
                int ci = kt / 9;
                int kk = kt - ci * 9;
                int si = (kk << 7) + p;
                float4 w4 = ((const float4*)sampW)[si];
                short4 i4 = sampI[si];
                const float* xp = xb + ci * HW;
                float v = w4.x * xp[i4.x] + w4.y * xp[i4.y]
                        + w4.z * xp[i4.z] + w4.w * xp[i4.w];
                __nv_bfloat16 h = __float2bfloat16(v);
                float rr = v - __bfloat162float(h);
                hs[s] = __bfloat16_as_ushort(h);
                ls[s] = __bfloat16_as_ushort(__float2bfloat16(rr));
            }
            int off = p * APAD + ktq * 8;
            *(ushort4*)(sm + SM_A + off)         = make_ushort4(hs[0], hs[1], hs[2], hs[3]);
            *(ushort4*)(sm + SM_A + 10240 + off) = make_ushort4(ls[0], ls[1], ls[2], ls[3]);
        }

        // ---- load B tile via cp.async (hi+lo, 2048 x 16B) ----
        {
            const unsigned char* src = g_wB + (size_t)c * 32768;
#pragma unroll
            for (int t = 0; t < 4; t++) {
                int j = t * NTH + tid;      // 0..2047
                int part = j >> 10;
                int jj = j & 1023;
                int oc = jj >> 2, k16 = jj & 3;
                cpa16(Bu + part * 20480 + oc * BPAD + k16 * 16,
                      src + part * 16384 + oc * 64 + k16 * 16);
            }
            asm volatile("cp.async.commit_group;" ::: "memory");
            asm volatile("cp.async.wait_group 0;" ::: "memory");
        }
        __syncthreads();

        // ---- GEMM: 2 k16 steps, 3 passes ----
#pragma unroll
        for (int ks = 0; ks < 2; ks++) {
            uint32_t ah[2][4], al[2][4];
            const int arow = lane & 15;
            const int acol = ((lane >> 4) << 4) + ks * 32;
#pragma unroll
            for (int mt = 0; mt < 2; mt++) {
                uint32_t addr = Au + (uint32_t)((warp_m + mt * 16 + arow) * APAD + acol);
                ldm_x4(addr, ah[mt]);
                ldm_x4(addr + 10240, al[mt]);
            }
#pragma unroll
            for (int np = 0; np < 4; np++) {
                uint32_t bh[4], bl[4];
                uint32_t baddr = Bu + (uint32_t)((warp_n + np * 16 + (lane & 15)) * BPAD
                                                 + ((lane >> 4) << 4) + ks * 32);
                ldm_x4(baddr, bh);
                ldm_x4(baddr + 20480, bl);
#pragma unroll
                for (int mt = 0; mt < 2; mt++) {
                    float* a0 = acc[mt][np * 2];
                    float* a1 = acc[mt][np * 2 + 1];
                    mma_bf16(a0, ah[mt], bh[0], bh[2]);
                    mma_bf16(a0, ah[mt], bl[0], bl[2]);
                    mma_bf16(a0, al[mt], bh[0], bh[2]);
                    mma_bf16(a1, ah[mt], bh[1], bh[3]);
                    mma_bf16(a1, ah[mt], bl[1], bl[3]);
                    mma_bf16(a1, al[mt], bh[1], bh[3]);
                }
            }
        }
    }

    // ---- epilogue ----
    float* ob = out + (size_t)b * COUT * HW + pixbase;
#pragma unroll
    for (int mt = 0; mt < 2; mt++)
#pragma unroll
        for (int nb = 0; nb < 8; nb++) {
            int col0 = warp_n + nb * 8 + (lane & 3) * 2;
            float b0 = __ldg(bias + col0);
            float b1 = __ldg(bias + col0 + 1);
            int row0 = warp_m + mt * 16 + (lane >> 2);
#pragma unroll
            for (int r = 0; r < 4; r++) {
                int row = row0 + ((r >> 1) & 1) * 8;
                int col = col0 + (r & 1);
                ob[(size_t)col * HW + row] = acc[mt][nb][r] + ((r & 1) ? b1 : b0);
            }
        }
}

extern "C" void kernel_launch(void* const* d_in, const int* in_sizes, int n_in,
                              void* d_out, int out_size)
{
    const float* x    = (const float*)d_in[0];
    const float* offw = (const float*)d_in[1];
    const float* offb = (const float*)d_in[2];
    const float* modw = (const float*)d_in[3];
    const float* modb = (const float*)d_in[4];
    const float* wgt  = (const float*)d_in[5];
    const float* bias = (const float*)d_in[6];
    float* out = (float*)d_out;

    static bool attr_done = false;
    if (!attr_done) {
        cudaFuncSetAttribute(dconv_kernel, cudaFuncAttributeMaxDynamicSharedMemorySize,
                             SMEM_BYTES);
        attr_done = true;
    }

    prep_wB<<<2304, 256>>>(wgt);                // 72*256*32 threads

    dim3 g1(4, 8, 8);
    prep_kernel<<<g1, 128>>>(x, offw, offb, modw, modb);

    dim3 g2(HW / 128, 1, 8);                    // 32 x 8 = 256 blocks
    dconv_kernel<<<g2, NTH, SMEM_BYTES>>>(x, bias, out);
}

// round 7
// speedup vs baseline: 2.7273x; 1.0390x over previous
#include <cuda_runtime.h>
#include <cuda_bf16.h>
#include <math.h>
#include <stdint.h>

#define B_    8
#define CIN   256
#define COUT  256
#define HH    64
#define WW    64
#define HW    4096
#define K2    9
#define KTOT  (CIN * K2)   // 2304
#define NCH   72           // K chunks of 32

typedef unsigned long long ull;

// Scratch: per (b, k, pixel): 4 corner indices + 4 corner weights (mask-premultiplied)
__device__ int   g_cidx[B_ * K2 * HW * 4];
__device__ float g_cwgt[B_ * K2 * HW * 4];
// Pre-split weights, chunked: [chunk][hi 16KB | lo 16KB]; row=oc (64B = 32 bf16)
__device__ unsigned char g_wB[NCH * 32768];

// ---------------- helpers ----------------
__device__ __forceinline__ ull fma2(ull a, ull b, ull c) {
    ull d;
    asm("fma.rn.f32x2 %0, %1, %2, %3;" : "=l"(d) : "l"(a), "l"(b), "l"(c));
    return d;
}
__device__ __forceinline__ ull pack2(float lo, float hi) {
    ull r;
    asm("mov.b64 %0, {%1, %2};" : "=l"(r) : "f"(lo), "f"(hi));
    return r;
}
__device__ __forceinline__ void unpack2(ull v, float& lo, float& hi) {
    asm("mov.b64 {%0, %1}, %2;" : "=f"(lo), "=f"(hi) : "l"(v));
}
__device__ __forceinline__ uint32_t smem_u32(const void* p) {
    return (uint32_t)__cvta_generic_to_shared(p);
}
__device__ __forceinline__ void cpa16(uint32_t dst, const void* src) {
    asm volatile("cp.async.ca.shared.global [%0], [%1], 16;" :: "r"(dst), "l"(src));
}
__device__ __forceinline__ void ldm_x4(uint32_t addr, uint32_t* r) {
    asm volatile("ldmatrix.sync.aligned.m8n8.x4.shared.b16 {%0,%1,%2,%3}, [%4];"
                 : "=r"(r[0]), "=r"(r[1]), "=r"(r[2]), "=r"(r[3]) : "r"(addr));
}
__device__ __forceinline__ void mma_bf16(float* d, const uint32_t* a,
                                         uint32_t b0, uint32_t b1) {
    asm volatile("mma.sync.aligned.m16n8k16.row.col.f32.bf16.bf16.f32 "
                 "{%0,%1,%2,%3}, {%4,%5,%6,%7}, {%8,%9}, {%0,%1,%2,%3};"
                 : "+f"(d[0]), "+f"(d[1]), "+f"(d[2]), "+f"(d[3])
                 : "r"(a[0]), "r"(a[1]), "r"(a[2]), "r"(a[3]), "r"(b0), "r"(b1));
}

// =====================================================================
// Kernel 0: split main weight to bf16 hi/lo, chunked layout for cp.async
// =====================================================================
__global__ void __launch_bounds__(256) prep_wB(const float* __restrict__ wgt)
{
    int i = blockIdx.x * 256 + threadIdx.x;    // 72*256*32 = 589824
    int ktl = i & 31;
    int oc  = (i >> 5) & 255;
    int cc  = i >> 13;
    int kt  = cc * 32 + ktl;
    int c   = kt / 9;
    int k   = kt - c * 9;
    float v = wgt[((size_t)oc * CIN + c) * 9 + k];
    __nv_bfloat16 h = __float2bfloat16(v);
    float r = v - __bfloat162float(h);
    __nv_bfloat16 l = __float2bfloat16(r);
    unsigned char* base = g_wB + (size_t)cc * 32768;
    *(unsigned short*)(base + oc * 64 + ktl * 2)         = __bfloat16_as_ushort(h);
    *(unsigned short*)(base + 16384 + oc * 64 + ktl * 2) = __bfloat16_as_ushort(l);
}

// =====================================================================
// Stage 1: offset(18ch) + mask(9ch) 3x3 conv, fused epilogue that emits
// bilinear corner indices/weights (weights premultiplied by the mask).
// =====================================================================
__global__ void __launch_bounds__(128) prep_kernel(
    const float* __restrict__ x,
    const float* __restrict__ offw, const float* __restrict__ offb,
    const float* __restrict__ modw, const float* __restrict__ modb)
{
    __shared__ float xs[10][18];
    __shared__ float ws2[9 * 28];

    const int b  = blockIdx.z;
    const int h0 = blockIdx.y * 8;
    const int w0 = blockIdx.x * 16;
    const int tid = threadIdx.x;
    const int th = tid >> 4, tw = tid & 15;
    const int h = h0 + th, w = w0 + tw;
    const float* xb = x + (size_t)b * CIN * HW;

    ull acc2[14];
#pragma unroll
    for (int i = 0; i < 14; i++) acc2[i] = 0ull;

    for (int c = 0; c < CIN; c++) {
        for (int i = tid; i < 180; i += 128) {
            int r = i / 18, cc = i - r * 18;
            int gh = h0 - 1 + r, gw = w0 - 1 + cc;
            float v = 0.f;
            if (gh >= 0 && gh < HH && gw >= 0 && gw < WW) v = xb[c * HW + gh * WW + gw];
            (&xs[0][0])[i] = v;
        }
        for (int i = tid; i < 252; i += 128) {
            int k = i / 28, oc = i - k * 28;
            float v;
            if (oc < 18)      v = offw[(oc * CIN + c) * 9 + k];
            else if (oc < 27) v = modw[((oc - 18) * CIN + c) * 9 + k];
            else              v = 0.f;
            ws2[i] = v;
        }
        __syncthreads();

        ull wd[9];
#pragma unroll
        for (int k = 0; k < 9; k++) {
            float v = xs[th + k / 3][tw + k % 3];
            wd[k] = pack2(v, v);
        }
#pragma unroll
        for (int k = 0; k < 9; k++) {
            const float* row = ws2 + k * 28;
#pragma unroll
            for (int u = 0; u < 7; u++) {
                ulonglong2 tt = *(const ulonglong2*)(row + u * 4);
                acc2[2 * u]     = fma2(wd[k], tt.x, acc2[2 * u]);
                acc2[2 * u + 1] = fma2(wd[k], tt.y, acc2[2 * u + 1]);
            }
        }
        __syncthreads();
    }

    float acc[28];
#pragma unroll
    for (int u = 0; u < 14; u++) unpack2(acc2[u], acc[2 * u], acc[2 * u + 1]);

    const int pix = h * WW + w;
#pragma unroll
    for (int k = 0; k < 9; k++) {
        float dy = acc[2 * k]     + offb[2 * k];
        float dx = acc[2 * k + 1] + offb[2 * k + 1];
        float mz = acc[18 + k]    + modb[k];
        float m  = 2.f / (1.f + expf(-mz));

        float py = dy + (float)(h - 1 + k / 3);
        float px = dx + (float)(w - 1 + (k % 3));
        float y0f = floorf(py), x0f = floorf(px);
        float ly = py - y0f, lx = px - x0f;
        int y0 = (int)y0f, x0 = (int)x0f;

        int4 id; float4 wt;
        {
            int yy = y0, xx = x0; float wv = (1.f - ly) * (1.f - lx);
            bool v = (yy >= 0) && (yy < HH) && (xx >= 0) && (xx < WW);
            id.x = min(max(yy, 0), HH - 1) * WW + min(max(xx, 0), WW - 1);
            wt.x = v ? wv * m : 0.f;
        }
        {
            int yy = y0, xx = x0 + 1; float wv = (1.f - ly) * lx;
            bool v = (yy >= 0) && (yy < HH) && (xx >= 0) && (xx < WW);
            id.y = min(max(yy, 0), HH - 1) * WW + min(max(xx, 0), WW - 1);
            wt.y = v ? wv * m : 0.f;
        }
        {
            int yy = y0 + 1, xx = x0; float wv = ly * (1.f - lx);
            bool v = (yy >= 0) && (yy < HH) && (xx >= 0) && (xx < WW);
            id.z = min(max(yy, 0), HH - 1) * WW + min(max(xx, 0), WW - 1);
            wt.z = v ? wv * m : 0.f;
        }
        {
            int yy = y0 + 1, xx = x0 + 1; float wv = ly * lx;
            bool v = (yy >= 0) && (yy < HH) && (xx >= 0) && (xx < WW);
            id.w = min(max(yy, 0), HH - 1) * WW + min(max(xx, 0), WW - 1);
            wt.w = v ? wv * m : 0.f;
        }
        int slot = (b * K2 + k) * HW + pix;
        ((int4*)g_cidx)[slot]   = id;
        ((float4*)g_cwgt)[slot] = wt;
    }
}

// =====================================================================
// Stage 2: fused im2col + 3-pass split-bf16 warp-MMA GEMM, pipelined:
//   - A and B double-buffered in smem
//   - cp.async B(c+1) issued at iter top, waited at iter end
//   - gather LDGs for c+1 issued in halves, hidden under the GEMM halves
// Block: 128 pixels x 256 ocs, 512 thr / 16 warps (warp tile 32x64).
// =====================================================================
#define NTH 512
#define APAD 80
#define BPAD 80
#define ABUF 20480           // hi 10240 + lo 10240 per buffer
#define BBUF 40960           // hi 20480 + lo 20480 per buffer
// smem byte offsets
#define SM_SAMPW 0           // 18432
#define SM_SAMPI 18432       // 9216
#define SM_A     27648       // 2 x 20480
#define SM_B     68608       // 2 x 40960
#define SMEM_BYTES 150528

__global__ void __launch_bounds__(NTH)
dconv_kernel(const float* __restrict__ x,
             const float* __restrict__ bias, float* __restrict__ out)
{
    extern __shared__ unsigned char sm[];
    const uint32_t smb = smem_u32(sm);
    float*  sampW = (float*)(sm + SM_SAMPW);
    short4* sampI = (short4*)(sm + SM_SAMPI);

    const int b = blockIdx.z;
    const int pixbase = blockIdx.x * 128;
    const int tid = threadIdx.x;
    const int lane = tid & 31;
    const int wid = tid >> 5;
    const int warp_m = (wid & 3) * 32;
    const int warp_n = (wid >> 2) * 64;
    const float* xb = x + (size_t)b * CIN * HW;

    // sampling tables for this block's 128 pixels
    for (int i = tid; i < 1152; i += NTH) {
        int k = i >> 7, p = i & 127;
        int slot = (b * K2 + k) * HW + pixbase + p;
        ((float4*)sampW)[i] = ((const float4*)g_cwgt)[slot];
        int4 id = ((const int4*)g_cidx)[slot];
        short4 s;
        s.x = (short)id.x; s.y = (short)id.y; s.z = (short)id.z; s.w = (short)id.w;
        sampI[i] = s;
    }
    __syncthreads();

    float acc[2][8][4];
#pragma unroll
    for (int mt = 0; mt < 2; mt++)
#pragma unroll
        for (int nb = 0; nb < 8; nb++)
#pragma unroll
            for (int r = 0; r < 4; r++) acc[mt][nb][r] = 0.f;

    const int pp  = tid & 127;        // this thread's production pixel
    const int ktq = tid >> 7;         // base kt-quad (j adds 4*j)

// issue cp.async of B chunk cc into buffer bb
#define B_ISSUE(cc, bb) do {                                                     \
    const unsigned char* _src = g_wB + (size_t)(cc) * 32768;                     \
    uint32_t _Bu = smb + SM_B + (bb) * BBUF;                                     \
    _Pragma("unroll")                                                            \
    for (int _t = 0; _t < 4; _t++) {                                             \
        int _j = _t * NTH + tid;                                                 \
        int _part = _j >> 10;                                                    \
        int _jj = _j & 1023;                                                     \
        int _oc = _jj >> 2, _k16 = _jj & 3;                                      \
        cpa16(_Bu + _part * 20480 + _oc * BPAD + _k16 * 16,                      \
              _src + _part * 16384 + _oc * 64 + _k16 * 16);                      \
    }                                                                            \
    asm volatile("cp.async.commit_group;" ::: "memory");                         \
} while (0)

// prefetch 4 samples x 4 corners of chunk cc, half jj, into pre[16]
#define PREFETCH(jj, cc, pre) do {                                               \
    _Pragma("unroll")                                                            \
    for (int _s = 0; _s < 4; _s++) {                                             \
        int _kt = (cc) * 32 + (ktq + 4 * (jj)) * 4 + _s;                         \
        int _ci = _kt / 9;                                                       \
        int _kk = _kt - _ci * 9;                                                 \
        short4 _i4 = sampI[(_kk << 7) + pp];                                     \
        const float* _xp = xb + _ci * HW;                                        \
        (pre)[_s * 4 + 0] = _xp[_i4.x];                                          \
        (pre)[_s * 4 + 1] = _xp[_i4.y];                                          \
        (pre)[_s * 4 + 2] = _xp[_i4.z];                                          \
        (pre)[_s * 4 + 3] = _xp[_i4.w];                                          \
    }                                                                            \
} while (0)

// combine pre[16] -> A buffer bb, half jj of chunk cc
#define COMBINE(jj, cc, pre, bb) do {                                            \
    unsigned short _hs[4], _ls[4];                                               \
    _Pragma("unroll")                                                            \
    for (int _s = 0; _s < 4; _s++) {                                             \
        int _kt = (cc) * 32 + (ktq + 4 * (jj)) * 4 + _s;                         \
        int _ci = _kt / 9;                                                       \
        int _kk = _kt - _ci * 9;                                                 \
        float4 _w4 = ((const float4*)sampW)[(_kk << 7) + pp];                    \
        float _v = _w4.x * (pre)[_s * 4 + 0] + _w4.y * (pre)[_s * 4 + 1]         \
                 + _w4.z * (pre)[_s * 4 + 2] + _w4.w * (pre)[_s * 4 + 3];        \
        __nv_bfloat16 _h = __float2bfloat16(_v);                                 \
        float _rr = _v - __bfloat162float(_h);                                   \
        _hs[_s] = __bfloat16_as_ushort(_h);                                      \
        _ls[_s] = __bfloat16_as_ushort(__float2bfloat16(_rr));                   \
    }                                                                            \
    int _off = pp * APAD + (ktq + 4 * (jj)) * 8;                                 \
    unsigned char* _Ab = sm + SM_A + (bb) * ABUF;                                \
    *(ushort4*)(_Ab + _off)         = make_ushort4(_hs[0], _hs[1], _hs[2], _hs[3]); \
    *(ushort4*)(_Ab + 10240 + _off) = make_ushort4(_ls[0], _ls[1], _ls[2], _ls[3]); \
} while (0)

// one K16 step of the GEMM on buffer bb
#define GEMM_KS(ks, bb) do {                                                     \
    uint32_t _Au = smb + SM_A + (bb) * ABUF;                                     \
    uint32_t _Bu = smb + SM_B + (bb) * BBUF;                                     \
    uint32_t _ah[2][4], _al[2][4];                                               \
    const int _arow = lane & 15;                                                 \
    const int _acol = ((lane >> 4) << 4) + (ks) * 32;                            \
    _Pragma("unroll")                                                            \
    for (int _mt = 0; _mt < 2; _mt++) {                                          \
        uint32_t _ad = _Au + (uint32_t)((warp_m + _mt * 16 + _arow) * APAD + _acol); \
        ldm_x4(_ad, _ah[_mt]);                                                   \
        ldm_x4(_ad + 10240, _al[_mt]);                                           \
    }                                                                            \
    _Pragma("unroll")                                                            \
    for (int _np = 0; _np < 4; _np++) {                                          \
        uint32_t _bh[4], _bl[4];                                                 \
        uint32_t _bd = _Bu + (uint32_t)((warp_n + _np * 16 + (lane & 15)) * BPAD \
                                        + ((lane >> 4) << 4) + (ks) * 32);       \
        ldm_x4(_bd, _bh);                                                        \
        ldm_x4(_bd + 20480, _bl);                                                \
        _Pragma("unroll")                                                        \
        for (int _mt = 0; _mt < 2; _mt++) {                                      \
            float* _a0 = acc[_mt][_np * 2];                                      \
            float* _a1 = acc[_mt][_np * 2 + 1];                                  \
            mma_bf16(_a0, _ah[_mt], _bh[0], _bh[2]);                             \
            mma_bf16(_a0, _ah[_mt], _bl[0], _bl[2]);                             \
            mma_bf16(_a0, _al[_mt], _bh[0], _bh[2]);                             \
            mma_bf16(_a1, _ah[_mt], _bh[1], _bh[3]);                             \
            mma_bf16(_a1, _ah[_mt], _bl[1], _bl[3]);                             \
            mma_bf16(_a1, _al[_mt], _bh[1], _bh[3]);                             \
        }                                                                        \
    }                                                                            \
} while (0)

    // ---- prologue: stage chunk 0 ----
    {
        B_ISSUE(0, 0);
        float pre0[16];
        PREFETCH(0, 0, pre0);
        COMBINE(0, 0, pre0, 0);
        PREFETCH(1, 0, pre0);
        COMBINE(1, 0, pre0, 0);
        asm volatile("cp.async.wait_group 0;" ::: "memory");
    }
    __syncthreads();

    // ---- main pipelined loop ----
    for (int c = 0; c < NCH; c++) {
        const int cur = c & 1;
        const int nxt = cur ^ 1;
        const bool more = (c < NCH - 1);

        if (more) B_ISSUE(c + 1, nxt);

        float pre[16];
        if (more) PREFETCH(0, c + 1, pre);
        GEMM_KS(0, cur);
        if (more) {
            COMBINE(0, c + 1, pre, nxt);
            PREFETCH(1, c + 1, pre);
        }
        GEMM_KS(1, cur);
        if (more) COMBINE(1, c + 1, pre, nxt);

        asm volatile("cp.async.wait_group 0;" ::: "memory");
        __syncthreads();
    }

    // ---- epilogue ----
    float* ob = out + (size_t)b * COUT * HW + pixbase;
#pragma unroll
    for (int mt = 0; mt < 2; mt++)
#pragma unroll
        for (int nb = 0; nb < 8; nb++) {
            int col0 = warp_n + nb * 8 + (lane & 3) * 2;
            float b0 = __ldg(bias + col0);
            float b1 = __ldg(bias + col0 + 1);
            int row0 = warp_m + mt * 16 + (lane >> 2);
#pragma unroll
            for (int r = 0; r < 4; r++) {
                int row = row0 + ((r >> 1) & 1) * 8;
                int col = col0 + (r & 1);
                ob[(size_t)col * HW + row] = acc[mt][nb][r] + ((r & 1) ? b1 : b0);
            }
        }
}

extern "C" void kernel_launch(void* const* d_in, const int* in_sizes, int n_in,
                              void* d_out, int out_size)
{
    const float* x    = (const float*)d_in[0];
    const float* offw = (const float*)d_in[1];
    const float* offb = (const float*)d_in[2];
    const float* modw = (const float*)d_in[3];
    const float* modb = (const float*)d_in[4];
    const float* wgt  = (const float*)d_in[5];
    const float* bias = (const float*)d_in[6];
    float* out = (float*)d_out;

    static bool attr_done = false;
    if (!attr_done) {
        cudaFuncSetAttribute(dconv_kernel, cudaFuncAttributeMaxDynamicSharedMemorySize,
                             SMEM_BYTES);
        attr_done = true;
    }

    prep_wB<<<2304, 256>>>(wgt);                // 72*256*32 threads

    dim3 g1(4, 8, 8);
    prep_kernel<<<g1, 128>>>(x, offw, offb, modw, modb);

    dim3 g2(HW / 128, 1, 8);                    // 32 x 8 = 256 blocks
    dconv_kernel<<<g2, NTH, SMEM_BYTES>>>(x, bias, out);
}

// round 9
// speedup vs baseline: 3.6341x; 1.3325x over previous
#include <cuda_runtime.h>
#include <cuda_bf16.h>
#include <math.h>
#include <stdint.h>

#define B_    8
#define CIN   256
#define COUT  256
#define HH    64
#define WW    64
#define HW    4096
#define K2    9
#define KTOT  (CIN * K2)   // 2304
#define NCH   72           // K chunks of 32; kt' = k*256 + c  (k fixed per chunk)

typedef unsigned long long ull;

// Scratch: per (b, k, pixel): 4 corner indices + 4 corner weights (mask-premultiplied)
__device__ int   g_cidx[B_ * K2 * HW * 4];
__device__ float g_cwgt[B_ * K2 * HW * 4];
// Pre-converted tf32 weights, chunked: [chunk][oc][32 kt'-cols], 128B rows
__device__ uint32_t g_wB[NCH * 8192];

// ---------------- helpers ----------------
__device__ __forceinline__ ull fma2(ull a, ull b, ull c) {
    ull d;
    asm("fma.rn.f32x2 %0, %1, %2, %3;" : "=l"(d) : "l"(a), "l"(b), "l"(c));
    return d;
}
__device__ __forceinline__ ull pack2(float lo, float hi) {
    ull r;
    asm("mov.b64 %0, {%1, %2};" : "=l"(r) : "f"(lo), "f"(hi));
    return r;
}
__device__ __forceinline__ void unpack2(ull v, float& lo, float& hi) {
    asm("mov.b64 {%0, %1}, %2;" : "=f"(lo), "=f"(hi) : "l"(v));
}
__device__ __forceinline__ uint32_t smem_u32(const void* p) {
    return (uint32_t)__cvta_generic_to_shared(p);
}
__device__ __forceinline__ void cpa16(uint32_t dst, const void* src) {
    asm volatile("cp.async.ca.shared.global [%0], [%1], 16;" :: "r"(dst), "l"(src));
}
__device__ __forceinline__ void ldm_x4(uint32_t addr, uint32_t* r) {
    asm volatile("ldmatrix.sync.aligned.m8n8.x4.shared.b16 {%0,%1,%2,%3}, [%4];"
                 : "=r"(r[0]), "=r"(r[1]), "=r"(r[2]), "=r"(r[3]) : "r"(addr));
}
__device__ __forceinline__ uint32_t f2tf32(float f) {
    uint32_t r;
    asm("cvt.rna.tf32.f32 %0, %1;" : "=r"(r) : "f"(f));
    return r;
}
__device__ __forceinline__ void mma_tf32(float* d, const uint32_t* a,
                                         uint32_t b0, uint32_t b1) {
    asm volatile("mma.sync.aligned.m16n8k8.row.col.f32.tf32.tf32.f32 "
                 "{%0,%1,%2,%3}, {%4,%5,%6,%7}, {%8,%9}, {%0,%1,%2,%3};"
                 : "+f"(d[0]), "+f"(d[1]), "+f"(d[2]), "+f"(d[3])
                 : "r"(a[0]), "r"(a[1]), "r"(a[2]), "r"(a[3]), "r"(b0), "r"(b1));
}

// =====================================================================
// Kernel 0: convert main weight to tf32, kt' = k*256 + c ordering,
// chunked [cc][oc][32] for cp.async
// =====================================================================
__global__ void __launch_bounds__(256) prep_wB(const float* __restrict__ wgt)
{
    int i = blockIdx.x * 256 + threadIdx.x;    // 72*256*32 = 589824
    int ktl = i & 31;
    int oc  = (i >> 5) & 255;
    int cc  = i >> 13;
    int ktp = cc * 32 + ktl;                   // kt' = k*256 + c
    int k   = ktp >> 8;
    int c   = ktp & 255;
    float v = wgt[((size_t)oc * CIN + c) * 9 + k];
    g_wB[cc * 8192 + oc * 32 + ktl] = f2tf32(v);
}

// =====================================================================
// Stage 1: offset(18ch) + mask(9ch) 3x3 conv, fused epilogue that emits
// bilinear corner indices/weights (weights premultiplied by the mask).
// =====================================================================
__global__ void __launch_bounds__(128) prep_kernel(
    const float* __restrict__ x,
    const float* __restrict__ offw, const float* __restrict__ offb,
    const float* __restrict__ modw, const float* __restrict__ modb)
{
    __shared__ float xs[10][18];
    __shared__ float ws2[9 * 28];

    const int b  = blockIdx.z;
    const int h0 = blockIdx.y * 8;
    const int w0 = blockIdx.x * 16;
    const int tid = threadIdx.x;
    const int th = tid >> 4, tw = tid & 15;
    const int h = h0 + th, w = w0 + tw;
    const float* xb = x + (size_t)b * CIN * HW;

    ull acc2[14];
#pragma unroll
    for (int i = 0; i < 14; i++) acc2[i] = 0ull;

    for (int c = 0; c < CIN; c++) {
        for (int i = tid; i < 180; i += 128) {
            int r = i / 18, cc = i - r * 18;
            int gh = h0 - 1 + r, gw = w0 - 1 + cc;
            float v = 0.f;
            if (gh >= 0 && gh < HH && gw >= 0 && gw < WW) v = xb[c * HW + gh * WW + gw];
            (&xs[0][0])[i] = v;
        }
        for (int i = tid; i < 252; i += 128) {
            int k = i / 28, oc = i - k * 28;
            float v;
            if (oc < 18)      v = offw[(oc * CIN + c) * 9 + k];
            else if (oc < 27) v = modw[((oc - 18) * CIN + c) * 9 + k];
            else              v = 0.f;
            ws2[i] = v;
        }
        __syncthreads();

        ull wd[9];
#pragma unroll
        for (int k = 0; k < 9; k++) {
            float v = xs[th + k / 3][tw + k % 3];
            wd[k] = pack2(v, v);
        }
#pragma unroll
        for (int k = 0; k < 9; k++) {
            const float* row = ws2 + k * 28;
#pragma unroll
            for (int u = 0; u < 7; u++) {
                ulonglong2 tt = *(const ulonglong2*)(row + u * 4);
                acc2[2 * u]     = fma2(wd[k], tt.x, acc2[2 * u]);
                acc2[2 * u + 1] = fma2(wd[k], tt.y, acc2[2 * u + 1]);
            }
        }
        __syncthreads();
    }

    float acc[28];
#pragma unroll
    for (int u = 0; u < 14; u++) unpack2(acc2[u], acc[2 * u], acc[2 * u + 1]);

    const int pix = h * WW + w;
#pragma unroll
    for (int k = 0; k < 9; k++) {
        float dy = acc[2 * k]     + offb[2 * k];
        float dx = acc[2 * k + 1] + offb[2 * k + 1];
        float mz = acc[18 + k]    + modb[k];
        float m  = 2.f / (1.f + expf(-mz));

        float py = dy + (float)(h - 1 + k / 3);
        float px = dx + (float)(w - 1 + (k % 3));
        float y0f = floorf(py), x0f = floorf(px);
        float ly = py - y0f, lx = px - x0f;
        int y0 = (int)y0f, x0 = (int)x0f;

        int4 id; float4 wt;
        {
            int yy = y0, xx = x0; float wv = (1.f - ly) * (1.f - lx);
            bool v = (yy >= 0) && (yy < HH) && (xx >= 0) && (xx < WW);
            id.x = min(max(yy, 0), HH - 1) * WW + min(max(xx, 0), WW - 1);
            wt.x = v ? wv * m : 0.f;
        }
        {
            int yy = y0, xx = x0 + 1; float wv = (1.f - ly) * lx;
            bool v = (yy >= 0) && (yy < HH) && (xx >= 0) && (xx < WW);
            id.y = min(max(yy, 0), HH - 1) * WW + min(max(xx, 0), WW - 1);
            wt.y = v ? wv * m : 0.f;
        }
        {
            int yy = y0 + 1, xx = x0; float wv = ly * (1.f - lx);
            bool v = (yy >= 0) && (yy < HH) && (xx >= 0) && (xx < WW);
            id.z = min(max(yy, 0), HH - 1) * WW + min(max(xx, 0), WW - 1);
            wt.z = v ? wv * m : 0.f;
        }
        {
            int yy = y0 + 1, xx = x0 + 1; float wv = ly * lx;
            bool v = (yy >= 0) && (yy < HH) && (xx >= 0) && (xx < WW);
            id.w = min(max(yy, 0), HH - 1) * WW + min(max(xx, 0), WW - 1);
            wt.w = v ? wv * m : 0.f;
        }
        int slot = (b * K2 + k) * HW + pix;
        ((int4*)g_cidx)[slot]   = id;
        ((float4*)g_cwgt)[slot] = wt;
    }
}

// =====================================================================
// Stage 2: fused im2col + SINGLE-PASS TF32 warp-MMA GEMM, pipelined.
// kt' = k*256 + c ordering -> each 32-chunk has ONE k: idx/weights loaded
// once per thread per chunk; channel gathers use immediate-offset LDGs.
// Block: 128 pixels x 256 ocs, 512 thr / 16 warps (warp tile 32x64).
// =====================================================================
#define NTH 512
#define APAD 144             // 32 tf32 = 128B + 16B pad (conflict-free)
#define BPAD 144
#define ABUF 18432           // 128 * 144
#define BBUF 36864           // 256 * 144
// smem byte offsets
#define SM_SAMPW 0           // 18432
#define SM_SAMPI 18432       // 9216
#define SM_A     27648       // 2 x 18432
#define SM_B     64512       // 2 x 36864
#define SMEM_BYTES 138240

__global__ void __launch_bounds__(NTH)
dconv_kernel(const float* __restrict__ x,
             const float* __restrict__ bias, float* __restrict__ out)
{
    extern __shared__ unsigned char sm[];
    const uint32_t smb = smem_u32(sm);
    float*  sampW = (float*)(sm + SM_SAMPW);
    short4* sampI = (short4*)(sm + SM_SAMPI);

    const int b = blockIdx.z;
    const int pixbase = blockIdx.x * 128;
    const int tid = threadIdx.x;
    const int lane = tid & 31;
    const int wid = tid >> 5;
    const int warp_m = (wid & 3) * 32;
    const int warp_n = (wid >> 2) * 64;
    const float* xb = x + (size_t)b * CIN * HW;

    // sampling tables for this block's 128 pixels
    for (int i = tid; i < 1152; i += NTH) {
        int k = i >> 7, p = i & 127;
        int slot = (b * K2 + k) * HW + pixbase + p;
        ((float4*)sampW)[i] = ((const float4*)g_cwgt)[slot];
        int4 id = ((const int4*)g_cidx)[slot];
        short4 s;
        s.x = (short)id.x; s.y = (short)id.y; s.z = (short)id.z; s.w = (short)id.w;
        sampI[i] = s;
    }
    __syncthreads();

    float acc[2][8][4];
#pragma unroll
    for (int mt = 0; mt < 2; mt++)
#pragma unroll
        for (int nb = 0; nb < 8; nb++)
#pragma unroll
            for (int r = 0; r < 4; r++) acc[mt][nb][r] = 0.f;

    const int pp = tid & 127;         // this thread's production pixel
    const int cq = tid >> 7;          // channel group: channels cq*8..cq*8+7

// issue cp.async of B chunk cc into buffer bb (32KB, 128B rows -> 144B rows)
#define B_ISSUE(cc, bb) do {                                                     \
    const unsigned char* _src = (const unsigned char*)(g_wB + (cc) * 8192);      \
    uint32_t _Bu = smb + SM_B + (bb) * BBUF;                                     \
    _Pragma("unroll")                                                            \
    for (int _t = 0; _t < 4; _t++) {                                             \
        int _j = _t * NTH + tid;                                                 \
        int _oc = _j >> 3, _seg = _j & 7;                                        \
        cpa16(_Bu + _oc * BPAD + _seg * 16, _src + _oc * 128 + _seg * 16);       \
    }                                                                            \
    asm volatile("cp.async.commit_group;" ::: "memory");                         \
} while (0)

// one K8 step of the tf32 GEMM on buffer bb; ks in 0..3
#define GEMM_KS(ks, bb) do {                                                     \
    uint32_t _Au = smb + SM_A + (bb) * ABUF;                                     \
    uint32_t _Bu = smb + SM_B + (bb) * BBUF;                                     \
    uint32_t _ah[2][4];                                                          \
    const int _arow = lane & 15;                                                 \
    const int _aoff = ((lane >> 4) << 4) + (ks) * 32;                            \
    _Pragma("unroll")                                                            \
    for (int _mt = 0; _mt < 2; _mt++) {                                          \
        ldm_x4(_Au + (uint32_t)((warp_m + _mt * 16 + _arow) * APAD + _aoff),     \
               _ah[_mt]);                                                        \
    }                                                                            \
    const int _brow = (lane & 7) + ((lane >> 4) << 3);                           \
    const int _boff = ((lane >> 3) & 1) * 16 + (ks) * 32;                        \
    _Pragma("unroll")                                                            \
    for (int _nt = 0; _nt < 4; _nt++) {                                          \
        uint32_t _bf[4];                                                         \
        ldm_x4(_Bu + (uint32_t)((warp_n + _nt * 16 + _brow) * BPAD + _boff),     \
               _bf);                                                             \
        _Pragma("unroll")                                                        \
        for (int _mt = 0; _mt < 2; _mt++) {                                      \
            mma_tf32(acc[_mt][_nt * 2],     _ah[_mt], _bf[0], _bf[1]);           \
            mma_tf32(acc[_mt][_nt * 2 + 1], _ah[_mt], _bf[2], _bf[3]);           \
        }                                                                        \
    }                                                                            \
} while (0)

    // ---- prologue: stage chunk 0 (k=0, channels 0..31) ----
    {
        B_ISSUE(0, 0);
        int si = pp;                   // (k=0) << 7 | pp
        short4 i4 = sampI[si];
        float4 w4 = ((const float4*)sampW)[si];
        const float* base = xb + (size_t)(cq * 8) * HW;
        const float* pa = base + i4.x;
        const float* pb = base + i4.y;
        const float* pc = base + i4.z;
        const float* pd = base + i4.w;
        uint32_t* Arow = (uint32_t*)(sm + SM_A + pp * APAD + cq * 32);
#pragma unroll
        for (int j = 0; j < 8; j++) {
            float v = w4.x * pa[j * HW] + w4.y * pb[j * HW]
                    + w4.z * pc[j * HW] + w4.w * pd[j * HW];
            Arow[j] = f2tf32(v);
        }
        asm volatile("cp.async.wait_group 0;" ::: "memory");
    }
    __syncthreads();

    // ---- main pipelined loop ----
    for (int c = 0; c < NCH; c++) {
        const int cur = c & 1;
        const int nxt = cur ^ 1;
        const bool more = (c < NCH - 1);

        float4 w4 = make_float4(0.f, 0.f, 0.f, 0.f);
        const float *pa = xb, *pb = xb, *pc = xb, *pd = xb;
        if (more) {
            B_ISSUE(c + 1, nxt);
            const int kn  = (c + 1) >> 3;
            const int c0n = ((c + 1) & 7) * 32;
            int si = (kn << 7) + pp;
            short4 i4 = sampI[si];
            w4 = ((const float4*)sampW)[si];
            const float* base = xb + (size_t)(c0n + cq * 8) * HW;
            pa = base + i4.x; pb = base + i4.y; pc = base + i4.z; pd = base + i4.w;
        }

        float pre[16];
#pragma unroll
        for (int j = 0; j < 16; j++) pre[j] = 0.f;
        if (more) {
#pragma unroll
            for (int j = 0; j < 4; j++) {
                pre[j * 4 + 0] = pa[j * HW];
                pre[j * 4 + 1] = pb[j * HW];
                pre[j * 4 + 2] = pc[j * HW];
                pre[j * 4 + 3] = pd[j * HW];
            }
        }

        GEMM_KS(0, cur);
        GEMM_KS(1, cur);

        if (more) {
            uint32_t av[4];
#pragma unroll
            for (int j = 0; j < 4; j++)
                av[j] = f2tf32(w4.x * pre[j * 4 + 0] + w4.y * pre[j * 4 + 1]
                             + w4.z * pre[j * 4 + 2] + w4.w * pre[j * 4 + 3]);
            *(uint4*)(sm + SM_A + nxt * ABUF + pp * APAD + cq * 32) =
                make_uint4(av[0], av[1], av[2], av[3]);
            // prefetch second half (channels +4..+7)
#pragma unroll
            for (int j = 0; j < 4; j++) {
                pre[j * 4 + 0] = pa[(j + 4) * HW];
                pre[j * 4 + 1] = pb[(j + 4) * HW];
                pre[j * 4 + 2] = pc[(j + 4) * HW];
                pre[j * 4 + 3] = pd[(j + 4) * HW];
            }
        }

        GEMM_KS(2, cur);
        GEMM_KS(3, cur);

        if (more) {
            uint32_t av[4];
#pragma unroll
            for (int j = 0; j < 4; j++)
                av[j] = f2tf32(w4.x * pre[j * 4 + 0] + w4.y * pre[j * 4 + 1]
                             + w4.z * pre[j * 4 + 2] + w4.w * pre[j * 4 + 3]);
            *(uint4*)(sm + SM_A + nxt * ABUF + pp * APAD + cq * 32 + 16) =
                make_uint4(av[0], av[1], av[2], av[3]);
        }

        asm volatile("cp.async.wait_group 0;" ::: "memory");
        __syncthreads();
    }

    // ---- epilogue ----
    float* ob = out + (size_t)b * COUT * HW + pixbase;
#pragma unroll
    for (int mt = 0; mt < 2; mt++)
#pragma unroll
        for (int nb = 0; nb < 8; nb++) {
            int col0 = warp_n + nb * 8 + (lane & 3) * 2;
            float b0 = __ldg(bias + col0);
            float b1 = __ldg(bias + col0 + 1);
            int row0 = warp_m + mt * 16 + (lane >> 2);
#pragma unroll
            for (int r = 0; r < 4; r++) {
                int row = row0 + ((r >> 1) & 1) * 8;
                int col = col0 + (r & 1);
                ob[(size_t)col * HW + row] = acc[mt][nb][r] + ((r & 1) ? b1 : b0);
            }
        }
}

extern "C" void kernel_launch(void* const* d_in, const int* in_sizes, int n_in,
                              void* d_out, int out_size)
{
    const float* x    = (const float*)d_in[0];
    const float* offw = (const float*)d_in[1];
    const float* offb = (const float*)d_in[2];
    const float* modw = (const float*)d_in[3];
    const float* modb = (const float*)d_in[4];
    const float* wgt  = (const float*)d_in[5];
    const float* bias = (const float*)d_in[6];
    float* out = (float*)d_out;

    static bool attr_done = false;
    if (!attr_done) {
        cudaFuncSetAttribute(dconv_kernel, cudaFuncAttributeMaxDynamicSharedMemorySize,
                             SMEM_BYTES);
        attr_done = true;
    }

    prep_wB<<<2304, 256>>>(wgt);                // 72*256*32 threads

    dim3 g1(4, 8, 8);
    prep_kernel<<<g1, 128>>>(x, offw, offb, modw, modb);

    dim3 g2(HW / 128, 1, 8);                    // 32 x 8 = 256 blocks
    dconv_kernel<<<g2, NTH, SMEM_BYTES>>>(x, bias, out);
}